// round 1
// baseline (speedup 1.0000x reference)
#include <cuda_runtime.h>

// RMAC: x[64,2048,16,16] -> out[64, 14*2048], L2-normalized per batch row.
// Regions: 1x(16x16 @0,0) + 4x(10x10 @{0,4}^2) + 9x(8x8 @{0,3,6}^2)

#define BATCH 64
#define CH    2048
#define NREG  14
#define OUTB  (NREG * CH)   // 28672

__device__ float g_sumsq[BATCH];

__global__ void rmac_zero() {
    if (threadIdx.x < BATCH) g_sumsq[threadIdx.x] = 0.f;
}

__global__ __launch_bounds__(256) void rmac_pool(const float* __restrict__ x,
                                                 float* __restrict__ out) {
    // 8 warps per block; warp w handles plane = blockIdx.x*8 + w (one (b,c) pair).
    __shared__ float tile[8][16 * 20];   // padded rows: stride 20 floats (16B aligned)
    __shared__ float hsum[8][6 * 16];    // 6 column windows x 16 rows
    __shared__ float wsq[8];

    const int w    = threadIdx.x >> 5;
    const int lane = threadIdx.x & 31;
    const int plane = blockIdx.x * 8 + w;
    const int b = plane >> 11;         // /2048
    const int c = plane & 2047;

    // Coalesced load: plane is 256 contiguous floats = 64 float4s.
    const float4* px = (const float4*)(x + (size_t)plane * 256);
    float4 f0 = px[lane];
    float4 f1 = px[lane + 32];
    {
        int row = lane >> 2;
        int col = (lane & 3) << 2;
        *(float4*)&tile[w][row * 20 + col]       = f0;
        *(float4*)&tile[w][(row + 8) * 20 + col] = f1;
    }
    __syncwarp();

    // Step 1: per-row prefix sums -> 6 horizontal (column-window) sums.
    // hw0: cols [0,16)  hw1: [0,10)  hw2: [4,14)  hw3: [0,8)  hw4: [3,11)  hw5: [6,14)
    if (lane < 16) {
        const float* tr = &tile[w][lane * 20];
        float pr[17];
        pr[0] = 0.f;
        float p = 0.f;
        #pragma unroll
        for (int cc = 0; cc < 16; ++cc) { p += tr[cc]; pr[cc + 1] = p; }
        hsum[w][0 * 16 + lane] = pr[16];
        hsum[w][1 * 16 + lane] = pr[10];
        hsum[w][2 * 16 + lane] = pr[14] - pr[4];
        hsum[w][3 * 16 + lane] = pr[8];
        hsum[w][4 * 16 + lane] = pr[11] - pr[3];
        hsum[w][5 * 16 + lane] = pr[14] - pr[6];
    }
    __syncwarp();

    // Step 2: lanes 0..13 compute one region average each.
    // Region order (matches torch cat): r0 = l1; r1..r4 = l2 row-major; r5..r13 = l3 row-major.
    float v = 0.f;
    if (lane < 14) {
        int hw, rlo, len; float inv;
        if (lane == 0)      { hw = 0;               rlo = 0;                len = 16; inv = 1.f / 256.f; }
        else if (lane < 5)  { int i = lane - 1; hw = 1 + (i & 1);  rlo = 4 * (i >> 1); len = 10; inv = 1.f / 100.f; }
        else                { int i = lane - 5; hw = 3 + (i % 3);  rlo = 3 * (i / 3);  len = 8;  inv = 1.f / 64.f; }
        const float* hs = &hsum[w][hw * 16];
        float s = 0.f;
        for (int r = rlo; r < rlo + len; ++r) s += hs[r];
        v = s * inv;
        out[(size_t)b * OUTB + lane * CH + c] = v;
    }

    // Sum of squares: warp reduce -> block reduce -> one atomic per block.
    float sq = v * v;
    #pragma unroll
    for (int o = 16; o; o >>= 1) sq += __shfl_xor_sync(0xffffffffu, sq, o);
    if (lane == 0) wsq[w] = sq;
    __syncthreads();
    if (threadIdx.x == 0) {
        float t = 0.f;
        #pragma unroll
        for (int i = 0; i < 8; ++i) t += wsq[i];
        atomicAdd(&g_sumsq[b], t);   // all 8 warps in a block share the same b
    }
}

__global__ __launch_bounds__(256) void rmac_norm(float* __restrict__ out) {
    int i = blockIdx.x * 256 + threadIdx.x;      // float4 index
    int b = i / (OUTB / 4);                      // 7168 float4s per batch row
    float norm  = sqrtf(g_sumsq[b]);
    float scale = 1.f / fmaxf(norm, 1e-12f);
    float4 v = ((const float4*)out)[i];
    v.x *= scale; v.y *= scale; v.z *= scale; v.w *= scale;
    ((float4*)out)[i] = v;
}

extern "C" void kernel_launch(void* const* d_in, const int* in_sizes, int n_in,
                              void* d_out, int out_size) {
    const float* x = (const float*)d_in[0];
    float* out = (float*)d_out;

    rmac_zero<<<1, 64>>>();
    rmac_pool<<<(BATCH * CH) / 8, 256>>>(x, out);            // 16384 blocks
    rmac_norm<<<(BATCH * OUTB / 4) / 256, 256>>>(out);       // 1792 blocks
}

// round 2
// speedup vs baseline: 1.4148x; 1.4148x over previous
#include <cuda_runtime.h>

// RMAC: x[64,2048,16,16] -> out[64, 14*2048], L2-normalized per batch row.
// Regions: 1x(16x16 @0,0) + 4x(10x10 @{0,4}^2) + 9x(8x8 @{0,3,6}^2)

#define BATCH 64
#define CH    2048
#define NREG  14
#define OUTB  (NREG * CH)          // 28672
#define PLANES (BATCH * CH)        // 131072
#define PPB   16                   // planes per block (2 per warp, 8 warps)
#define NBLK  (PLANES / PPB)       // 8192
#define HS    112                  // hsum plane stride (mod 32 == 16: conflict-free)

__device__ float g_part[NBLK];     // per-block partial sum-of-squares (overwritten each run)

__global__ __launch_bounds__(256) void rmac_pool(const float* __restrict__ x,
                                                 float* __restrict__ out) {
    __shared__ float tile[PPB * 320];      // per plane: 16 rows, stride 20 floats
    __shared__ float hsum[PPB * HS];       // per plane: 6 windows x 16 rows (vertical prefixes)
    __shared__ float sval[NREG * 17];      // staged outputs [region][plane], padded
    __shared__ float wsq[8];

    const int t    = threadIdx.x;
    const int w    = t >> 5;
    const int lane = t & 31;
    const int pb   = blockIdx.x * PPB;     // first plane of block (same batch: 16 | 2048)
    const int b    = pb >> 11;
    const int c0   = pb & 2047;

    // ---- Load: warp w loads planes 2w, 2w+1 (512 contiguous floats) ----
    const float4* pw = (const float4*)(x + (size_t)(pb + 2 * w) * 256);
    #pragma unroll
    for (int k = 0; k < 4; ++k) {
        int i = lane + k * 32;             // float4 index within the 2 planes
        float4 f = pw[i];
        int pl = 2 * w + (i >> 6);
        int e  = i & 63;
        *(float4*)&tile[pl * 320 + (e >> 2) * 20 + (e & 3) * 4] = f;
    }
    __syncwarp();

    // ---- Row phase: lane -> (plane = 2w + lane/16, row = lane%16) ----
    const int pl  = 2 * w + (lane >> 4);
    const int row = lane & 15;
    const float* tr = &tile[pl * 320 + row * 20];
    float4 A = *(const float4*)tr;
    float4 B4 = *(const float4*)(tr + 4);
    float4 C4 = *(const float4*)(tr + 8);
    float4 D4 = *(const float4*)(tr + 12);

    float pr3  = A.x + A.y + A.z;
    float pr4  = pr3 + A.w;
    float pr6  = pr4 + B4.x + B4.y;
    float pr8  = pr6 + B4.z + B4.w;
    float pr10 = pr8 + C4.x + C4.y;
    float pr11 = pr10 + C4.z;
    float pr14 = pr11 + C4.w + D4.x + D4.y;
    float pr16 = pr14 + D4.z + D4.w;

    float h0 = pr16;          // cols [0,16)
    float h1 = pr10;          // cols [0,10)
    float h2 = pr14 - pr4;    // cols [4,14)
    float h3 = pr8;           // cols [0,8)
    float h4 = pr11 - pr3;    // cols [3,11)
    float h5 = pr14 - pr6;    // cols [6,14)

    // ---- Cooperative vertical inclusive prefix over rows (width-16 segments) ----
    #pragma unroll
    for (int d = 1; d < 16; d <<= 1) {
        float u0 = __shfl_up_sync(0xffffffffu, h0, d, 16);
        float u1 = __shfl_up_sync(0xffffffffu, h1, d, 16);
        float u2 = __shfl_up_sync(0xffffffffu, h2, d, 16);
        float u3 = __shfl_up_sync(0xffffffffu, h3, d, 16);
        float u4 = __shfl_up_sync(0xffffffffu, h4, d, 16);
        float u5 = __shfl_up_sync(0xffffffffu, h5, d, 16);
        if (row >= d) { h0 += u0; h1 += u1; h2 += u2; h3 += u3; h4 += u4; h5 += u5; }
    }
    float* P = &hsum[pl * HS];
    P[0 * 16 + row] = h0;
    P[1 * 16 + row] = h1;
    P[2 * 16 + row] = h2;
    P[3 * 16 + row] = h3;
    P[4 * 16 + row] = h4;
    P[5 * 16 + row] = h5;
    __syncwarp();

    // ---- Region extraction: lane -> (plane, region = lane%16 if <14) ----
    float v = 0.f;
    const int r = lane & 15;
    if (r < NREG) {
        int hw, rlo, rhi; float inv;
        if (r == 0)      { hw = 0; rlo = 0; rhi = 15; inv = 1.f / 256.f; }
        else if (r < 5)  { int i = r - 1; hw = 1 + (i & 1); rlo = 4 * (i >> 1); rhi = rlo + 9; inv = 0.01f; }
        else             { int i = r - 5; hw = 3 + (i % 3); rlo = 3 * (i / 3); rhi = rlo + 7; inv = 1.f / 64.f; }
        const float* Pp = &hsum[pl * HS + hw * 16];
        float hi = Pp[rhi];
        float lo = (rlo > 0) ? Pp[rlo - 1] : 0.f;
        v = (hi - lo) * inv;
        sval[r * 17 + pl] = v;
    }

    // ---- Sum of squares: warp butterfly -> block -> per-block partial ----
    float sq = v * v;
    #pragma unroll
    for (int o = 16; o; o >>= 1) sq += __shfl_xor_sync(0xffffffffu, sq, o);
    if (lane == 0) wsq[w] = sq;
    __syncthreads();
    if (t == 0) {
        float tot = 0.f;
        #pragma unroll
        for (int i = 0; i < 8; ++i) tot += wsq[i];
        g_part[blockIdx.x] = tot;
    }

    // ---- Coalesced store: 14 regions x 16 planes ----
    if (t < NREG * PPB) {
        int rr = t >> 4, p = t & 15;
        out[(size_t)b * OUTB + rr * CH + c0 + p] = sval[rr * 17 + p];
    }
}

__global__ __launch_bounds__(256) void rmac_norm(float* __restrict__ out) {
    __shared__ float warpsum[8];
    __shared__ float sscale;
    const int t = threadIdx.x;
    const int b = blockIdx.x / 28;         // 28 blocks per batch (7168 float4 / 256)

    // Reduce this batch's 128 per-block partials (L2-resident)
    float s = (t < 128) ? g_part[b * 128 + t] : 0.f;
    #pragma unroll
    for (int o = 16; o; o >>= 1) s += __shfl_xor_sync(0xffffffffu, s, o);
    if ((t & 31) == 0) warpsum[t >> 5] = s;
    __syncthreads();
    if (t == 0) {
        float tot = 0.f;
        #pragma unroll
        for (int i = 0; i < 8; ++i) tot += warpsum[i];
        sscale = 1.f / fmaxf(sqrtf(tot), 1e-12f);
    }
    __syncthreads();
    float scale = sscale;

    int i = blockIdx.x * 256 + t;          // float4 index into out
    float4 v = ((const float4*)out)[i];
    v.x *= scale; v.y *= scale; v.z *= scale; v.w *= scale;
    ((float4*)out)[i] = v;
}

extern "C" void kernel_launch(void* const* d_in, const int* in_sizes, int n_in,
                              void* d_out, int out_size) {
    const float* x = (const float*)d_in[0];
    float* out = (float*)d_out;

    rmac_pool<<<NBLK, 256>>>(x, out);                       // 8192 blocks
    rmac_norm<<<(BATCH * OUTB / 4) / 256, 256>>>(out);      // 1792 blocks
}

// round 3
// speedup vs baseline: 1.4834x; 1.0485x over previous
#include <cuda_runtime.h>

// RMAC: x[64,2048,16,16] -> out[64, 14*2048], L2-normalized per batch row.
// Regions: 1x(16x16 @0,0) + 4x(10x10 @{0,4}^2) + 9x(8x8 @{0,3,6}^2)

#define BATCH 64
#define CH    2048
#define NREG  14
#define OUTB  (NREG * CH)          // 28672
#define PLANES (BATCH * CH)        // 131072
#define PPB   16                   // planes per block (2 per warp, 8 warps)
#define NBLK  (PLANES / PPB)       // 8192
#define HS    112                  // hsum plane stride (mod 32 == 16: conflict-free)

__device__ float g_part[NBLK];     // per-block partial sum-of-squares (overwritten each run)

__global__ __launch_bounds__(256) void rmac_pool(const float* __restrict__ x,
                                                 float* __restrict__ out) {
    __shared__ float hsum[PPB * HS];       // per plane: 6 windows x 16 rows (vertical prefixes)
    __shared__ float sval[NREG * 17];      // staged outputs [region][plane], padded
    __shared__ float wsq[8];

    const int t    = threadIdx.x;
    const int w    = t >> 5;
    const int lane = t & 31;
    const int pb   = blockIdx.x * PPB;     // first plane of block (same batch: 16 | 2048)
    const int b    = pb >> 11;
    const int c0   = pb & 2047;

    // ---- Direct register load: lane -> (plane = 2w + lane/16, row = lane%16) ----
    const int pl  = 2 * w + (lane >> 4);
    const int row = lane & 15;
    const float4* pr = (const float4*)(x + (size_t)(pb + pl) * 256 + row * 16);
    float4 A  = pr[0];
    float4 B4 = pr[1];
    float4 C4 = pr[2];
    float4 D4 = pr[3];

    // ---- Row prefixes at the 8 needed cut points ----
    float pr3  = A.x + A.y + A.z;
    float pr4  = pr3 + A.w;
    float pr6  = pr4 + B4.x + B4.y;
    float pr8  = pr6 + B4.z + B4.w;
    float pr10 = pr8 + C4.x + C4.y;
    float pr11 = pr10 + C4.z;
    float pr14 = pr11 + C4.w + D4.x + D4.y;
    float pr16 = pr14 + D4.z + D4.w;

    float h0 = pr16;          // cols [0,16)
    float h1 = pr10;          // cols [0,10)
    float h2 = pr14 - pr4;    // cols [4,14)
    float h3 = pr8;           // cols [0,8)
    float h4 = pr11 - pr3;    // cols [3,11)
    float h5 = pr14 - pr6;    // cols [6,14)

    // ---- Cooperative vertical inclusive prefix over rows (width-16 segments) ----
    #pragma unroll
    for (int d = 1; d < 16; d <<= 1) {
        float u0 = __shfl_up_sync(0xffffffffu, h0, d, 16);
        float u1 = __shfl_up_sync(0xffffffffu, h1, d, 16);
        float u2 = __shfl_up_sync(0xffffffffu, h2, d, 16);
        float u3 = __shfl_up_sync(0xffffffffu, h3, d, 16);
        float u4 = __shfl_up_sync(0xffffffffu, h4, d, 16);
        float u5 = __shfl_up_sync(0xffffffffu, h5, d, 16);
        if (row >= d) { h0 += u0; h1 += u1; h2 += u2; h3 += u3; h4 += u4; h5 += u5; }
    }
    float* P = &hsum[pl * HS];
    P[0 * 16 + row] = h0;
    P[1 * 16 + row] = h1;
    P[2 * 16 + row] = h2;
    P[3 * 16 + row] = h3;
    P[4 * 16 + row] = h4;
    P[5 * 16 + row] = h5;
    __syncwarp();

    // ---- Region extraction: lane -> (plane, region = lane%16 if <14) ----
    float v = 0.f;
    const int r = lane & 15;
    if (r < NREG) {
        int hw, rlo, rhi; float inv;
        if (r == 0)      { hw = 0; rlo = 0; rhi = 15; inv = 1.f / 256.f; }
        else if (r < 5)  { int i = r - 1; hw = 1 + (i & 1); rlo = 4 * (i >> 1); rhi = rlo + 9; inv = 0.01f; }
        else             { int i = r - 5; hw = 3 + (i % 3); rlo = 3 * (i / 3); rhi = rlo + 7; inv = 1.f / 64.f; }
        const float* Pp = &hsum[pl * HS + hw * 16];
        float hi = Pp[rhi];
        float lo = (rlo > 0) ? Pp[rlo - 1] : 0.f;
        v = (hi - lo) * inv;
        sval[r * 17 + pl] = v;
    }

    // ---- Sum of squares: warp butterfly -> block -> per-block partial ----
    float sq = v * v;
    #pragma unroll
    for (int o = 16; o; o >>= 1) sq += __shfl_xor_sync(0xffffffffu, sq, o);
    if (lane == 0) wsq[w] = sq;
    __syncthreads();
    if (t == 0) {
        float tot = 0.f;
        #pragma unroll
        for (int i = 0; i < 8; ++i) tot += wsq[i];
        g_part[blockIdx.x] = tot;
    }

    // ---- Coalesced store: 14 regions x 16 planes ----
    if (t < NREG * PPB) {
        int rr = t >> 4, p = t & 15;
        out[(size_t)b * OUTB + rr * CH + c0 + p] = sval[rr * 17 + p];
    }
}

// 448 blocks; each handles 1024 float4s (4 per thread); 7 blocks per batch row.
__global__ __launch_bounds__(256) void rmac_norm(float* __restrict__ out) {
    __shared__ float warpsum[8];
    __shared__ float sscale;
    const int t = threadIdx.x;
    const int b = blockIdx.x / 7;          // 7 blocks per batch (7168 float4 / 1024)

    // Reduce this batch's 128 per-block partials (L2-resident)
    float s = (t < 128) ? g_part[b * 128 + t] : 0.f;
    #pragma unroll
    for (int o = 16; o; o >>= 1) s += __shfl_xor_sync(0xffffffffu, s, o);
    if ((t & 31) == 0) warpsum[t >> 5] = s;
    __syncthreads();
    if (t == 0) {
        float tot = 0.f;
        #pragma unroll
        for (int i = 0; i < 8; ++i) tot += warpsum[i];
        sscale = 1.f / fmaxf(sqrtf(tot), 1e-12f);
    }
    __syncthreads();
    const float scale = sscale;

    float4* o4 = (float4*)out;
    const int base = blockIdx.x * 1024 + t;
    #pragma unroll
    for (int k = 0; k < 4; ++k) {
        int i = base + k * 256;
        float4 v = o4[i];
        v.x *= scale; v.y *= scale; v.z *= scale; v.w *= scale;
        o4[i] = v;
    }
}

extern "C" void kernel_launch(void* const* d_in, const int* in_sizes, int n_in,
                              void* d_out, int out_size) {
    const float* x = (const float*)d_in[0];
    float* out = (float*)d_out;

    rmac_pool<<<NBLK, 256>>>(x, out);        // 8192 blocks
    rmac_norm<<<448, 256>>>(out);            // 448 blocks, 4 float4/thread
}

// round 4
// speedup vs baseline: 1.5674x; 1.0567x over previous
#include <cuda_runtime.h>

// RMAC: x[64,2048,16,16] -> out[64, 14*2048], L2-normalized per batch row.
// Regions: 1x(16x16 @0,0) + 4x(10x10 @{0,4}^2) + 9x(8x8 @{0,3,6}^2)

#define BATCH 64
#define CH    2048
#define NREG  14
#define OUTB  (NREG * CH)          // 28672
#define PLANES (BATCH * CH)        // 131072
#define PPB   16                   // planes per block (2 per warp, 8 warps)
#define NBLK  (PLANES / PPB)       // 8192
#define HS    112                  // hsum plane stride (mod 32 == 16: conflict-free)

__device__ float g_part[NBLK];     // per-block partial sum-of-squares (overwritten each run)

__global__ __launch_bounds__(256) void rmac_pool(const float* __restrict__ x,
                                                 float* __restrict__ out) {
    __shared__ float hsum[PPB * HS];       // per plane: 6 windows x 16 rows (vertical prefixes)
    __shared__ float sval[NREG * 17];      // staged outputs [region][plane], padded
    __shared__ float wsq[8];

    const int t    = threadIdx.x;
    const int w    = t >> 5;
    const int lane = t & 31;
    const int pb   = blockIdx.x * PPB;     // first plane of block (same batch: 16 | 2048)
    const int b    = pb >> 11;
    const int c0   = pb & 2047;

    // ---- Direct register load (streaming): lane -> (plane = 2w + lane/16, row = lane%16) ----
    const int pl  = 2 * w + (lane >> 4);
    const int row = lane & 15;
    const float4* pr = (const float4*)(x + (size_t)(pb + pl) * 256 + row * 16);
    float4 A  = __ldcs(pr + 0);
    float4 B4 = __ldcs(pr + 1);
    float4 C4 = __ldcs(pr + 2);
    float4 D4 = __ldcs(pr + 3);

    // ---- Row prefixes at the 8 needed cut points ----
    float pr3  = A.x + A.y + A.z;
    float pr4  = pr3 + A.w;
    float pr6  = pr4 + B4.x + B4.y;
    float pr8  = pr6 + B4.z + B4.w;
    float pr10 = pr8 + C4.x + C4.y;
    float pr11 = pr10 + C4.z;
    float pr14 = pr11 + C4.w + D4.x + D4.y;
    float pr16 = pr14 + D4.z + D4.w;

    float h0 = pr16;          // cols [0,16)
    float h1 = pr10;          // cols [0,10)
    float h2 = pr14 - pr4;    // cols [4,14)
    float h3 = pr8;           // cols [0,8)
    float h4 = pr11 - pr3;    // cols [3,11)
    float h5 = pr14 - pr6;    // cols [6,14)

    // ---- Cooperative vertical inclusive prefix over rows (width-16 segments) ----
    #pragma unroll
    for (int d = 1; d < 16; d <<= 1) {
        float u0 = __shfl_up_sync(0xffffffffu, h0, d, 16);
        float u1 = __shfl_up_sync(0xffffffffu, h1, d, 16);
        float u2 = __shfl_up_sync(0xffffffffu, h2, d, 16);
        float u3 = __shfl_up_sync(0xffffffffu, h3, d, 16);
        float u4 = __shfl_up_sync(0xffffffffu, h4, d, 16);
        float u5 = __shfl_up_sync(0xffffffffu, h5, d, 16);
        if (row >= d) { h0 += u0; h1 += u1; h2 += u2; h3 += u3; h4 += u4; h5 += u5; }
    }
    float* P = &hsum[pl * HS];
    P[0 * 16 + row] = h0;
    P[1 * 16 + row] = h1;
    P[2 * 16 + row] = h2;
    P[3 * 16 + row] = h3;
    P[4 * 16 + row] = h4;
    P[5 * 16 + row] = h5;
    __syncwarp();

    // ---- Region extraction: lane -> (plane, region = lane%16 if <14) ----
    float v = 0.f;
    const int r = lane & 15;
    if (r < NREG) {
        int hw, rlo, rhi; float inv;
        if (r == 0)      { hw = 0; rlo = 0; rhi = 15; inv = 1.f / 256.f; }
        else if (r < 5)  { int i = r - 1; hw = 1 + (i & 1); rlo = 4 * (i >> 1); rhi = rlo + 9; inv = 0.01f; }
        else             { int i = r - 5; hw = 3 + (i % 3); rlo = 3 * (i / 3); rhi = rlo + 7; inv = 1.f / 64.f; }
        const float* Pp = &hsum[pl * HS + hw * 16];
        float hi = Pp[rhi];
        float lo = (rlo > 0) ? Pp[rlo - 1] : 0.f;
        v = (hi - lo) * inv;
        sval[r * 17 + pl] = v;
    }

    // ---- Sum of squares: warp butterfly -> block -> per-block partial ----
    float sq = v * v;
    #pragma unroll
    for (int o = 16; o; o >>= 1) sq += __shfl_xor_sync(0xffffffffu, sq, o);
    if (lane == 0) wsq[w] = sq;
    __syncthreads();
    if (t == 0) {
        float tot = 0.f;
        #pragma unroll
        for (int i = 0; i < 8; ++i) tot += wsq[i];
        g_part[blockIdx.x] = tot;
    }

    // ---- Coalesced store: 14 regions x 16 planes ----
    if (t < NREG * PPB) {
        int rr = t >> 4, p = t & 15;
        out[(size_t)b * OUTB + rr * CH + c0 + p] = sval[rr * 17 + p];
    }
}

// 448 blocks; each handles 1024 float4s (4 per thread); 7 blocks per batch row.
// PDL secondary: blocks go resident during pool's tail; grid-sync releases them.
__global__ __launch_bounds__(256) void rmac_norm(float* __restrict__ out) {
    __shared__ float warpsum[8];
    __shared__ float sscale;
    const int t = threadIdx.x;
    const int b = blockIdx.x / 7;          // 7 blocks per batch (7168 float4 / 1024)

#if __CUDA_ARCH__ >= 900
    cudaGridDependencySynchronize();       // wait for pool completion (PDL)
#endif

    // Issue the out loads FIRST (independent of the reduction) so their
    // latency overlaps the serial partial-reduce + barriers below.
    float4* o4 = (float4*)out;
    const int base = blockIdx.x * 1024 + t;
    float4 v0 = o4[base];
    float4 v1 = o4[base + 256];
    float4 v2 = o4[base + 512];
    float4 v3 = o4[base + 768];

    // Reduce this batch's 128 per-block partials (L2-resident)
    float s = (t < 128) ? g_part[b * 128 + t] : 0.f;
    #pragma unroll
    for (int o = 16; o; o >>= 1) s += __shfl_xor_sync(0xffffffffu, s, o);
    if ((t & 31) == 0) warpsum[t >> 5] = s;
    __syncthreads();
    if (t == 0) {
        float tot = 0.f;
        #pragma unroll
        for (int i = 0; i < 8; ++i) tot += warpsum[i];
        sscale = 1.f / fmaxf(sqrtf(tot), 1e-12f);
    }
    __syncthreads();
    const float scale = sscale;

    v0.x *= scale; v0.y *= scale; v0.z *= scale; v0.w *= scale;
    v1.x *= scale; v1.y *= scale; v1.z *= scale; v1.w *= scale;
    v2.x *= scale; v2.y *= scale; v2.z *= scale; v2.w *= scale;
    v3.x *= scale; v3.y *= scale; v3.z *= scale; v3.w *= scale;
    o4[base]       = v0;
    o4[base + 256] = v1;
    o4[base + 512] = v2;
    o4[base + 768] = v3;
}

extern "C" void kernel_launch(void* const* d_in, const int* in_sizes, int n_in,
                              void* d_out, int out_size) {
    const float* x = (const float*)d_in[0];
    float* out = (float*)d_out;

    rmac_pool<<<NBLK, 256>>>(x, out);        // 8192 blocks

    // Launch norm with Programmatic Stream Serialization (PDL): its blocks
    // become resident during pool's tail wave; cudaGridDependencySynchronize
    // inside the kernel enforces the data dependency.
    cudaLaunchConfig_t cfg = {};
    cfg.gridDim  = dim3(448);
    cfg.blockDim = dim3(256);
    cfg.dynamicSmemBytes = 0;
    cudaLaunchAttribute attrs[1];
    attrs[0].id = cudaLaunchAttributeProgrammaticStreamSerialization;
    attrs[0].val.programmaticStreamSerializationAllowed = 1;
    cfg.attrs = attrs;
    cfg.numAttrs = 1;
    cudaError_t e = cudaLaunchKernelEx(&cfg, rmac_norm, out);
    if (e != cudaSuccess) {
        // Fallback: plain launch (still correct, just no overlap)
        rmac_norm<<<448, 256>>>(out);
    }
}

// round 6
// speedup vs baseline: 1.6648x; 1.0621x over previous
#include <cuda_runtime.h>

// RMAC: x[64,2048,16,16] -> out[64, 14*2048], L2-normalized per batch row.
// Regions: 1x(16x16 @0,0) + 4x(10x10 @{0,4}^2) + 9x(8x8 @{0,3,6}^2)

#define BATCH 64
#define CH    2048
#define NREG  14
#define OUTB  (NREG * CH)          // 28672
#define PLANES (BATCH * CH)        // 131072
#define PPB   32                   // planes per block (4 per warp)
#define NBLK  (PLANES / PPB)       // 4096
#define PBB   (NBLK / BATCH)       // 64 pool blocks per batch
#define PS    104                  // hsum plane stride
#define WS    17                   // hsum window stride (odd: distinct banks)

__device__ float g_part[NBLK];     // per-pool-block partial sum-of-squares
__device__ float g_scale[BATCH];   // per-batch 1/norm

__global__ __launch_bounds__(256) void rmac_pool(const float* __restrict__ x,
                                                 float* __restrict__ out) {
    __shared__ float hsum[PPB * PS];     // 13312 B: [plane][window*17 + row]
    __shared__ float sval[NREG * 33];    // staged outputs [region][plane], padded
    __shared__ float wsq[8];

    const int t    = threadIdx.x;
    const int w    = t >> 5;
    const int lane = t & 31;
    const int pb   = blockIdx.x * PPB;   // 32 | 2048 -> block stays in one batch
    const int b    = pb >> 11;
    const int c0   = pb & 2047;

    // ---- Phase 1: lane -> (plane pair, row). 8 front-batched LDG.128. ----
    const int half = lane >> 4;          // which plane pair of this warp
    const int row  = lane & 15;
    const int lpA  = w * 4 + 2 * half;   // block-local plane; pair is lpA, lpA+1
    const float4* pA = (const float4*)(x + (size_t)(pb + lpA) * 256 + row * 16);
    float4 a0 = __ldcs(pA + 0), a1 = __ldcs(pA + 1), a2 = __ldcs(pA + 2), a3 = __ldcs(pA + 3);
    float4 e0 = __ldcs(pA + 64), e1 = __ldcs(pA + 65), e2 = __ldcs(pA + 66), e3 = __ldcs(pA + 67);

    // Horizontal window sums for one row:
    // h0=[0,16) h1=[0,10) h2=[4,14) h3=[0,8) h4=[3,11) h5=[6,14)
    {
        float p3  = a0.x + a0.y + a0.z;
        float p4  = p3 + a0.w;
        float p6  = p4 + a1.x + a1.y;
        float p8  = p6 + a1.z + a1.w;
        float p10 = p8 + a2.x + a2.y;
        float p11 = p10 + a2.z;
        float p14 = p11 + a2.w + a3.x + a3.y;
        float p16 = p14 + a3.z + a3.w;
        float* H = &hsum[lpA * PS + row];
        H[0 * WS] = p16;
        H[1 * WS] = p10;
        H[2 * WS] = p14 - p4;
        H[3 * WS] = p8;
        H[4 * WS] = p11 - p3;
        H[5 * WS] = p14 - p6;
    }
    {
        float p3  = e0.x + e0.y + e0.z;
        float p4  = p3 + e0.w;
        float p6  = p4 + e1.x + e1.y;
        float p8  = p6 + e1.z + e1.w;
        float p10 = p8 + e2.x + e2.y;
        float p11 = p10 + e2.z;
        float p14 = p11 + e2.w + e3.x + e3.y;
        float p16 = p14 + e3.z + e3.w;
        float* H = &hsum[(lpA + 1) * PS + row];
        H[0 * WS] = p16;
        H[1 * WS] = p10;
        H[2 * WS] = p14 - p4;
        H[3 * WS] = p8;
        H[4 * WS] = p11 - p3;
        H[5 * WS] = p14 - p6;
    }
    __syncwarp();

    // ---- Phase 2: lane -> (plane pp = lane>>3, window win = lane&7). ----
    // Serial vertical running prefix in registers (16 LDS).
    float sq = 0.f;
    const int pp  = lane >> 3;
    const int win = lane & 7;
    if (win < 6) {
        const int lp = w * 4 + pp;
        const float* base = &hsum[lp * PS + win * WS];
        float P[16];
        float run = 0.f;
        #pragma unroll
        for (int r = 0; r < 16; ++r) { run += base[r]; P[r] = run; }
        if (win == 0) {
            // l1: rows [0,16) -> region 0
            float v = P[15] * (1.f / 256.f);
            sval[lp] = v;
            sq = v * v;
        } else if (win < 3) {
            // l2 col-window win: rows [0,10)->region win, rows [4,14)->region win+2
            float v1 = P[9] * 0.01f;
            float v2 = (P[13] - P[3]) * 0.01f;
            sval[win * 33 + lp]       = v1;
            sval[(win + 2) * 33 + lp] = v2;
            sq = v1 * v1 + v2 * v2;
        } else {
            // l3 col-window win: rows [0,8)/[3,11)/[6,14) -> regions win+2, win+5, win+8
            float v1 = P[7] * (1.f / 64.f);
            float v2 = (P[10] - P[2]) * (1.f / 64.f);
            float v3 = (P[13] - P[5]) * (1.f / 64.f);
            sval[(win + 2) * 33 + lp] = v1;
            sval[(win + 5) * 33 + lp] = v2;
            sval[(win + 8) * 33 + lp] = v3;
            sq = v1 * v1 + v2 * v2 + v3 * v3;
        }
    }

    // ---- Sum of squares: warp butterfly -> block -> per-block partial ----
    #pragma unroll
    for (int o = 16; o; o >>= 1) sq += __shfl_xor_sync(0xffffffffu, sq, o);
    if (lane == 0) wsq[w] = sq;
    __syncthreads();
    if (t == 0) {
        float tot = 0.f;
        #pragma unroll
        for (int i = 0; i < 8; ++i) tot += wsq[i];
        g_part[blockIdx.x] = tot;
    }

    // ---- Coalesced store: 14 regions x 32 planes = 448 elems, 256 threads ----
    #pragma unroll
    for (int i = t; i < NREG * PPB; i += 256) {
        int rr = i >> 5, p = i & 31;
        out[(size_t)b * OUTB + rr * CH + c0 + p] = sval[rr * 33 + p];
    }
}

// 64 blocks x 64 threads: reduce each batch's 64 partials -> g_scale[b].
__global__ __launch_bounds__(64) void rmac_scale() {
#if __CUDA_ARCH__ >= 900
    cudaGridDependencySynchronize();
#endif
    __shared__ float ws[2];
    const int b = blockIdx.x, t = threadIdx.x;
    float s = g_part[b * PBB + t];
    #pragma unroll
    for (int o = 16; o; o >>= 1) s += __shfl_xor_sync(0xffffffffu, s, o);
    if ((t & 31) == 0) ws[t >> 5] = s;
    __syncthreads();
    if (t == 0) g_scale[b] = 1.f / fmaxf(sqrtf(ws[0] + ws[1]), 1e-12f);
}

// 896 blocks x 256 threads x 2 float4: pure streaming rescale, no block-level
// serialization (scale is one broadcast load).
__global__ __launch_bounds__(256) void rmac_norm(float* __restrict__ out) {
#if __CUDA_ARCH__ >= 900
    cudaGridDependencySynchronize();
#endif
    const int t = threadIdx.x;
    const int b = blockIdx.x / 14;          // 512 float4 per block; 7168 per batch
    float4* o4 = (float4*)out;
    const int base = blockIdx.x * 512 + t;
    float4 v0 = o4[base];
    float4 v1 = o4[base + 256];
    const float sc = __ldg(&g_scale[b]);
    v0.x *= sc; v0.y *= sc; v0.z *= sc; v0.w *= sc;
    v1.x *= sc; v1.y *= sc; v1.z *= sc; v1.w *= sc;
    o4[base]       = v0;
    o4[base + 256] = v1;
}

static inline void launch_pdl(void* fn, dim3 g, dim3 bk, void** args) {
    cudaLaunchConfig_t cfg = {};
    cfg.gridDim = g;
    cfg.blockDim = bk;
    cudaLaunchAttribute attrs[1];
    attrs[0].id = cudaLaunchAttributeProgrammaticStreamSerialization;
    attrs[0].val.programmaticStreamSerializationAllowed = 1;
    cfg.attrs = attrs;
    cfg.numAttrs = 1;
    cudaLaunchKernelExC(&cfg, fn, args);
}

extern "C" void kernel_launch(void* const* d_in, const int* in_sizes, int n_in,
                              void* d_out, int out_size) {
    const float* x = (const float*)d_in[0];
    float* out = (float*)d_out;

    rmac_pool<<<NBLK, 256>>>(x, out);       // 4096 blocks

    void* noargs[1] = {nullptr};
    launch_pdl((void*)rmac_scale, dim3(BATCH), dim3(64), noargs);

    void* nargs[] = {(void*)&out};
    launch_pdl((void*)rmac_norm, dim3(896), dim3(256), nargs);
}

// round 7
// speedup vs baseline: 1.9112x; 1.1480x over previous
#include <cuda_runtime.h>

// RMAC: x[64,2048,16,16] -> out[64, 14*2048], L2-normalized per batch row.
// Regions: 1x(16x16 @0,0) + 4x(10x10 @{0,4}^2) + 9x(8x8 @{0,3,6}^2)

#define BATCH 64
#define CH    2048
#define NREG  14
#define OUTB  (NREG * CH)          // 28672
#define PLANES (BATCH * CH)        // 131072
#define PPB   32                   // planes per block (4 per warp)
#define NBLK  (PLANES / PPB)       // 4096
#define PBB   (NBLK / BATCH)       // 64 pool blocks per batch
#define CSTR  20                   // cut-column row stride (floats)
#define PSTR  160                  // plane stride = 8 cuts * CSTR

__device__ float g_part[NBLK];     // per-pool-block partial sum-of-squares
__device__ float g_scale[BATCH];   // per-batch 1/norm

__global__ __launch_bounds__(256) void rmac_pool(const float* __restrict__ x,
                                                 float* __restrict__ out) {
    __shared__ float S[PPB * PSTR];      // 20 KB: [plane][cut][row] cut prefixes
    __shared__ float sval[NREG * 33];    // staged outputs [region][plane]
    __shared__ float wsq[8];

    const int t    = threadIdx.x;
    const int w    = t >> 5;
    const int lane = t & 31;
    const int pb   = blockIdx.x * PPB;   // 32 | 2048 -> block stays in one batch
    const int b    = pb >> 11;
    const int c0   = pb & 2047;

    // ---- Coalesced load: warp covers 4 planes = 256 float4, 8 per lane ----
    const float4* xw = (const float4*)(x + (size_t)(pb + w * 4) * 256);
    float4 f[8];
    #pragma unroll
    for (int k = 0; k < 8; ++k) f[k] = __ldcs(xw + 32 * k + lane);

    // ---- Phase 1: per float4 chunk, build the row's horizontal prefix cuts.
    // f[k] = quarter (lane&3) of row 8*(k&1)+(lane>>2) of plane (k>>1).
    // Cuts per quarter q: (2q, 2q+1) = (p3,p4)|(p6,p8)|(p10,p11)|(p14,p16).
    const int q      = lane & 3;
    const int rowoff = lane >> 2;
    #pragma unroll
    for (int k = 0; k < 8; ++k) {
        float xv = f[k].x, yv = f[k].y, zv = f[k].z, wv = f[k].w;
        float txy = xv + yv;
        float qs  = txy + zv + wv;
        // exclusive scan of quarter sums over the 4-lane row group
        float incl = qs;
        float s1 = __shfl_up_sync(0xffffffffu, incl, 1, 4);
        if (q >= 1) incl += s1;
        float s2 = __shfl_up_sync(0xffffffffu, incl, 2, 4);
        if (q >= 2) incl += s2;
        float Ex = incl - qs;
        float pa = Ex + txy + ((q == 0) ? zv : 0.f);      // p3|p6|p10|p14
        float pc = (q == 2) ? (Ex + txy + zv) : (Ex + qs); // p4|p8|p11|p16
        int lp  = w * 4 + (k >> 1);
        int row = 8 * (k & 1) + rowoff;
        S[lp * PSTR + (2 * q)     * CSTR + row] = pa;
        S[lp * PSTR + (2 * q + 1) * CSTR + row] = pc;
    }
    __syncwarp();

    // ---- Phase 2: lane = (plane pp, cut k2). Vertical prefix of one cut column.
    const int pp = lane >> 3;
    const int k2 = lane & 7;
    const float* col = &S[(w * 4 + pp) * PSTR + k2 * CSTR];
    float4 r0 = *(const float4*)(col + 0);
    float4 r1 = *(const float4*)(col + 4);
    float4 r2 = *(const float4*)(col + 8);
    float4 r3 = *(const float4*)(col + 12);
    float P[16];
    P[0]  = r0.x;          P[1]  = P[0]  + r0.y;  P[2]  = P[1]  + r0.z;  P[3]  = P[2]  + r0.w;
    P[4]  = P[3]  + r1.x;  P[5]  = P[4]  + r1.y;  P[6]  = P[5]  + r1.z;  P[7]  = P[6]  + r1.w;
    P[8]  = P[7]  + r2.x;  P[9]  = P[8]  + r2.y;  P[10] = P[9]  + r2.z;  P[11] = P[10] + r2.w;
    P[12] = P[11] + r3.x;  P[13] = P[12] + r3.y;  P[14] = P[13] + r3.z;  P[15] = P[14] + r3.w;

    // Range values of this cut column
    float A  = P[9];            // rows [0,10)
    float B  = P[13] - P[3];    // rows [4,14)
    float C  = P[7];            // rows [0,8)
    float D  = P[10] - P[2];    // rows [3,11)
    float E2 = P[13] - P[5];    // rows [6,14)
    float F  = P[15];           // rows [0,16)

    // Exchange: minuend lanes fetch subtrahend columns (k-5 and k-4 mod 8 in-group)
    const int base = lane & ~7;
    const int src5 = base | ((k2 + 3) & 7);   // k-5 mod 8
    const int src4 = base | ((k2 + 4) & 7);   // k-4 mod 8
    float rA5 = __shfl_sync(0xffffffffu, A,  src5);
    float rB5 = __shfl_sync(0xffffffffu, B,  src5);
    float rC5 = __shfl_sync(0xffffffffu, C,  src5);
    float rD5 = __shfl_sync(0xffffffffu, D,  src5);
    float rE5 = __shfl_sync(0xffffffffu, E2, src5);
    float rC4 = __shfl_sync(0xffffffffu, C,  src4);
    float rD4 = __shfl_sync(0xffffffffu, D,  src4);
    float rE4 = __shfl_sync(0xffffffffu, E2, src4);

    // Region emission. Cut ids: c0=p3 c1=p4 c2=p6 c3=p8 c4=p10 c5=p11 c6=p14 c7=p16
    // h1=c4 h2=c6-c1 h3=c3 h4=c5-c0 h5=c6-c2 h0=c7
    const int lp2 = w * 4 + pp;
    float sq = 0.f;
    if (k2 == 7) {
        float v0 = F * (1.f / 256.f);
        sval[0 * 33 + lp2] = v0;
        sq = v0 * v0;
    } else if (k2 == 4) {
        float v1 = A * 0.01f;                    // r1
        float v3 = B * 0.01f;                    // r3
        sval[1 * 33 + lp2] = v1;
        sval[3 * 33 + lp2] = v3;
        sq = v1 * v1 + v3 * v3;
    } else if (k2 == 6) {
        float v2  = (A  - rA5) * 0.01f;          // r2  (c6-c1)
        float v4  = (B  - rB5) * 0.01f;          // r4
        float v7  = (C  - rC4) * (1.f / 64.f);   // r7  (c6-c2)
        float v10 = (D  - rD4) * (1.f / 64.f);   // r10
        float v13 = (E2 - rE4) * (1.f / 64.f);   // r13
        sval[2  * 33 + lp2] = v2;
        sval[4  * 33 + lp2] = v4;
        sval[7  * 33 + lp2] = v7;
        sval[10 * 33 + lp2] = v10;
        sval[13 * 33 + lp2] = v13;
        sq = v2 * v2 + v4 * v4 + v7 * v7 + v10 * v10 + v13 * v13;
    } else if (k2 == 5) {
        float v6  = (C  - rC5) * (1.f / 64.f);   // r6  (c5-c0)
        float v9  = (D  - rD5) * (1.f / 64.f);   // r9
        float v12 = (E2 - rE5) * (1.f / 64.f);   // r12
        sval[6  * 33 + lp2] = v6;
        sval[9  * 33 + lp2] = v9;
        sval[12 * 33 + lp2] = v12;
        sq = v6 * v6 + v9 * v9 + v12 * v12;
    } else if (k2 == 3) {
        float v5  = C  * (1.f / 64.f);           // r5
        float v8  = D  * (1.f / 64.f);           // r8
        float v11 = E2 * (1.f / 64.f);           // r11
        sval[5  * 33 + lp2] = v5;
        sval[8  * 33 + lp2] = v8;
        sval[11 * 33 + lp2] = v11;
        sq = v5 * v5 + v8 * v8 + v11 * v11;
    }

    // ---- Sum of squares: warp butterfly -> block -> per-block partial ----
    #pragma unroll
    for (int o = 16; o; o >>= 1) sq += __shfl_xor_sync(0xffffffffu, sq, o);
    if (lane == 0) wsq[w] = sq;
    __syncthreads();
    if (t == 0) {
        float tot = 0.f;
        #pragma unroll
        for (int i = 0; i < 8; ++i) tot += wsq[i];
        g_part[blockIdx.x] = tot;
    }

    // ---- Coalesced store: 14 regions x 32 planes = 448 elems ----
    #pragma unroll
    for (int i = t; i < NREG * PPB; i += 256) {
        int rr = i >> 5, p = i & 31;
        out[(size_t)b * OUTB + rr * CH + c0 + p] = sval[rr * 33 + p];
    }
}

// 64 blocks x 64 threads: reduce each batch's 64 partials -> g_scale[b].
__global__ __launch_bounds__(64) void rmac_scale() {
#if __CUDA_ARCH__ >= 900
    cudaGridDependencySynchronize();
#endif
    __shared__ float ws[2];
    const int b = blockIdx.x, t = threadIdx.x;
    float s = g_part[b * PBB + t];
    #pragma unroll
    for (int o = 16; o; o >>= 1) s += __shfl_xor_sync(0xffffffffu, s, o);
    if ((t & 31) == 0) ws[t >> 5] = s;
    __syncthreads();
    if (t == 0) g_scale[b] = 1.f / fmaxf(sqrtf(ws[0] + ws[1]), 1e-12f);
}

// 896 blocks x 256 threads x 2 float4: pure streaming rescale.
__global__ __launch_bounds__(256) void rmac_norm(float* __restrict__ out) {
#if __CUDA_ARCH__ >= 900
    cudaGridDependencySynchronize();
#endif
    const int t = threadIdx.x;
    const int b = blockIdx.x / 14;          // 512 float4 per block; 7168 per batch
    float4* o4 = (float4*)out;
    const int base = blockIdx.x * 512 + t;
    float4 v0 = o4[base];
    float4 v1 = o4[base + 256];
    const float sc = __ldg(&g_scale[b]);
    v0.x *= sc; v0.y *= sc; v0.z *= sc; v0.w *= sc;
    v1.x *= sc; v1.y *= sc; v1.z *= sc; v1.w *= sc;
    o4[base]       = v0;
    o4[base + 256] = v1;
}

static inline void launch_pdl(void* fn, dim3 g, dim3 bk, void** args) {
    cudaLaunchConfig_t cfg = {};
    cfg.gridDim = g;
    cfg.blockDim = bk;
    cudaLaunchAttribute attrs[1];
    attrs[0].id = cudaLaunchAttributeProgrammaticStreamSerialization;
    attrs[0].val.programmaticStreamSerializationAllowed = 1;
    cfg.attrs = attrs;
    cfg.numAttrs = 1;
    cudaLaunchKernelExC(&cfg, fn, args);
}

extern "C" void kernel_launch(void* const* d_in, const int* in_sizes, int n_in,
                              void* d_out, int out_size) {
    const float* x = (const float*)d_in[0];
    float* out = (float*)d_out;

    rmac_pool<<<NBLK, 256>>>(x, out);       // 4096 blocks

    void* noargs[1] = {nullptr};
    launch_pdl((void*)rmac_scale, dim3(BATCH), dim3(64), noargs);

    void* nargs[] = {(void*)&out};
    launch_pdl((void*)rmac_norm, dim3(896), dim3(256), nargs);
}